// round 17
// baseline (speedup 1.0000x reference)
#include <cuda_runtime.h>
#include <cuda_fp16.h>
#include <cstdint>

// ============================================================================
// out[4096,16384] = f32( fp8( (x_fp8 @ w_fp8^T) / (xs*ws) + bias ) )
// R17: complete the fragment software-pipeline. R16 hoisted ks=0 LDSMs above
//      the cp.async batch (-88us). Now double-buffer fragments across ALL ks
//      steps: load frags(ks+1) before MMAs(ks), so every LDSM chain is issued
//      one MMA-batch ahead of its consumer. Prepass identical to R15/R16.
// ============================================================================

#define TOKENS   4096
#define NOUT     16384
#define KDIM     4096

#define TM       128
#define TN       128
#define TKB      128            // K-chunk bytes per smem row = 64 f16
#define KELEM    64
#define STAGES   3
#define NK_ITERS (KDIM / KELEM) // 64
#define ROWB     (KDIM * 2)

#define NTHREADS 128
#define STAGE_BYTES 16384
#define SMEM_TOTAL  (STAGES * 2 * STAGE_BYTES)   // 96 KB -> 2 CTAs/SM

#define N4X ((TOKENS * KDIM) / 4)
#define N4W ((NOUT   * KDIM) / 4)

__device__ __align__(128) uint8_t g_x16[(size_t)TOKENS * KDIM * 2];   // 32 MB
__device__ __align__(128) uint8_t g_w16[(size_t)NOUT   * KDIM * 2];   // 128 MB
__device__ unsigned g_absmax_bits[2];   // zeroed at load; re-zeroed by gemm tail
__device__ float    g_scales[2];        // relayed by quant (amax values)

// ---------------------------------------------------------------------------
__device__ __forceinline__ uint32_t smem_to_u32(const void* p) {
    uint32_t a;
    asm("{ .reg .u64 t; cvta.to.shared.u64 t, %1; cvt.u32.u64 %0, t; }" : "=r"(a) : "l"(p));
    return a;
}
__device__ __forceinline__ uint16_t cvt2_e4m3(float lo, float hi) {
    uint16_t r;
    asm("cvt.rn.satfinite.e4m3x2.f32 %0, %1, %2;" : "=h"(r) : "f"(hi), "f"(lo));
    return r;
}
__device__ __forceinline__ uint32_t e4m3x2_to_f16x2(uint16_t p) {
    uint32_t h2;
    asm("{ .reg .b16 t; mov.b16 t, %1; cvt.rn.f16x2.e4m3x2 %0, t; }" : "=r"(h2) : "h"(p));
    return h2;
}
__device__ __forceinline__ float2 dec2_e4m3(uint16_t p) {
    uint32_t h2 = e4m3x2_to_f16x2(p);
    __half2 h = *reinterpret_cast<__half2*>(&h2);
    return __half22float2(h);
}
__device__ __forceinline__ void cp_async16(uint32_t smem_dst, const void* gptr) {
    asm volatile("cp.async.cg.shared.global [%0], [%1], 16;" :: "r"(smem_dst), "l"(gptr));
}
__device__ __forceinline__ void cp_commit() {
    asm volatile("cp.async.commit_group;" ::: "memory");
}
template <int N>
__device__ __forceinline__ void cp_wait() {
    asm volatile("cp.async.wait_group %0;" :: "n"(N) : "memory");
}
__device__ __forceinline__ void mma_f16(float* c, const uint32_t* a, const uint32_t* b) {
    asm volatile(
        "mma.sync.aligned.m16n8k16.row.col.f32.f16.f16.f32 "
        "{%0,%1,%2,%3}, {%4,%5,%6,%7}, {%8,%9}, {%0,%1,%2,%3};"
        : "+f"(c[0]), "+f"(c[1]), "+f"(c[2]), "+f"(c[3])
        : "r"(a[0]), "r"(a[1]), "r"(a[2]), "r"(a[3]), "r"(b[0]), "r"(b[1]));
}
__device__ __forceinline__ void ldsm_x4(uint32_t addr,
                                        uint32_t& r0, uint32_t& r1,
                                        uint32_t& r2, uint32_t& r3) {
    asm volatile("ldmatrix.sync.aligned.m8n8.x4.shared.b16 {%0,%1,%2,%3}, [%4];"
                 : "=r"(r0), "=r"(r1), "=r"(r2), "=r"(r3) : "r"(addr));
}
__device__ __forceinline__ uint32_t swz(uint32_t row, uint32_t col) {
    return row * 128u + (((col >> 4) ^ (row & 7u)) << 4) + (col & 15u);
}

// ---------------------------------------------------------------------------
// Launch #1: fused absmax (82-83% DRAM — at floor)
#define AX_XBLK 1536
#define AX_WBLK 4608
__global__ void absmax_fused_kernel(const float4* __restrict__ x,
                                    const float4* __restrict__ w) {
    const int bx = blockIdx.x;
    const bool isX = bx < AX_XBLK;
    const float4* __restrict__ p = isX ? x : w;
    const int n4   = isX ? N4X : N4W;
    const int nblk = isX ? AX_XBLK : AX_WBLK;
    const int bid  = isX ? bx : bx - AX_XBLK;
    const int slot = isX ? 0 : 1;
    const int stride = nblk * blockDim.x;

    float m0 = 0.f, m1 = 0.f;
    for (int i = bid * blockDim.x + threadIdx.x; i < n4; i += 2 * stride) {
        float4 v = p[i];
        const int j = i + stride;
        if (j < n4) {
            float4 u = p[j];
            m1 = fmaxf(m1, fmaxf(fmaxf(fabsf(u.x), fabsf(u.y)),
                                 fmaxf(fabsf(u.z), fabsf(u.w))));
        }
        m0 = fmaxf(m0, fmaxf(fmaxf(fabsf(v.x), fabsf(v.y)),
                             fmaxf(fabsf(v.z), fabsf(v.w))));
    }
    float m = fmaxf(m0, m1);
    #pragma unroll
    for (int o = 16; o; o >>= 1) m = fmaxf(m, __shfl_xor_sync(0xffffffffu, m, o));
    __shared__ float sm[32];
    if ((threadIdx.x & 31) == 0) sm[threadIdx.x >> 5] = m;
    __syncthreads();
    if (threadIdx.x < 32) {
        float v = (threadIdx.x < (blockDim.x >> 5)) ? sm[threadIdx.x] : 0.f;
        #pragma unroll
        for (int o = 16; o; o >>= 1) v = fmaxf(v, __shfl_xor_sync(0xffffffffu, v, o));
        if (threadIdx.x == 0) atomicMax(&g_absmax_bits[slot], __float_as_uint(v));
    }
}

// ---------------------------------------------------------------------------
// Launch #2: fused quant; block 0 relays scales.
#define QT_XBLK 2048
#define QT_WBLK 6144
__global__ void quant_fused_kernel(const float4* __restrict__ x,
                                   const float4* __restrict__ w) {
    if (blockIdx.x == 0 && threadIdx.x < 2)
        g_scales[threadIdx.x] = __uint_as_float(g_absmax_bits[threadIdx.x]);

    const int bx = blockIdx.x;
    const bool isX = bx < QT_XBLK;
    const float4* __restrict__ in = isX ? x : w;
    uint4* __restrict__ out = isX ? (uint4*)g_x16 : (uint4*)g_w16;
    const int n8   = (isX ? N4X : N4W) / 2;
    const int nblk = isX ? QT_XBLK : QT_WBLK;
    const int bid  = isX ? bx : bx - QT_XBLK;
    const int stride = nblk * blockDim.x;

    float amax = __uint_as_float(g_absmax_bits[isX ? 0 : 1]);
    float s = 448.f / (amax + 1e-6f);

    for (int i = bid * blockDim.x + threadIdx.x; i < n8; i += 2 * stride) {
        const int j = i + stride;
        float4 a0 = in[2 * i];
        float4 a1 = in[2 * i + 1];
        float4 b0, b1;
        if (j < n8) { b0 = in[2 * j]; b1 = in[2 * j + 1]; }
        uint4 o0;
        o0.x = e4m3x2_to_f16x2(cvt2_e4m3(a0.x * s, a0.y * s));
        o0.y = e4m3x2_to_f16x2(cvt2_e4m3(a0.z * s, a0.w * s));
        o0.z = e4m3x2_to_f16x2(cvt2_e4m3(a1.x * s, a1.y * s));
        o0.w = e4m3x2_to_f16x2(cvt2_e4m3(a1.z * s, a1.w * s));
        out[i] = o0;
        if (j < n8) {
            uint4 o1;
            o1.x = e4m3x2_to_f16x2(cvt2_e4m3(b0.x * s, b0.y * s));
            o1.y = e4m3x2_to_f16x2(cvt2_e4m3(b0.z * s, b0.w * s));
            o1.z = e4m3x2_to_f16x2(cvt2_e4m3(b1.x * s, b1.y * s));
            o1.w = e4m3x2_to_f16x2(cvt2_e4m3(b1.z * s, b1.w * s));
            out[j] = o1;
        }
    }
}

// ---------------------------------------------------------------------------
// Launch #3: GEMM with full fragment double-buffering:
//   barrier -> LDSM frags(ks=0,buf0) -> cp.async issue ->
//   for ks: LDSM frags(ks+1, alt buf) ; MMA(ks, cur buf)
// ---------------------------------------------------------------------------
__global__ __launch_bounds__(NTHREADS, 2)
void gemm_kernel(const float* __restrict__ bias, float* __restrict__ out)
{
    extern __shared__ char smem[];
    const uint32_t smem_u32 = smem_to_u32(smem);

    const int tid  = threadIdx.x;
    const int wid  = tid >> 5;
    const int lid  = tid & 31;
    const int lr   = lid >> 2;
    const int lc   = lid & 3;
    const int warpM = wid & 1;
    const int warpN = wid >> 1;
    const int lt   = lid & 7;
    const int tile = lid >> 3;

    const unsigned mBase = blockIdx.x * TM;
    const unsigned nBase = blockIdx.y * TN;

    const uint8_t* __restrict__ gA = g_x16 + (size_t)mBase * ROWB;
    const uint8_t* __restrict__ gB = g_w16 + (size_t)nBase * ROWB;

    auto load_stage = [&](int st, int kc) {
        const unsigned kOff = (unsigned)kc * TKB;
        const uint32_t sa = smem_u32 + st * 2 * STAGE_BYTES;
        const uint32_t sb = sa + STAGE_BYTES;
        #pragma unroll
        for (int t = 0; t < 8; t++) {
            unsigned idx = tid + t * NTHREADS;
            unsigned row = idx >> 3, g = (idx & 7) << 4;
            cp_async16(sa + swz(row, g), gA + (size_t)row * ROWB + kOff + g);
        }
        #pragma unroll
        for (int t = 0; t < 8; t++) {
            unsigned idx = tid + t * NTHREADS;
            unsigned row = idx >> 3, g = (idx & 7) << 4;
            cp_async16(sb + swz(row, g), gB + (size_t)row * ROWB + kOff + g);
        }
    };

    float acc[4][8][4];
    #pragma unroll
    for (int mi = 0; mi < 4; mi++)
        #pragma unroll
        for (int ni = 0; ni < 8; ni++)
            #pragma unroll
            for (int q = 0; q < 4; q++) acc[mi][ni][q] = 0.f;

    const unsigned aRow     = (unsigned)(warpM * 64 + (tile & 1) * 8 + lt);
    const unsigned aColHalf = (unsigned)((tile >> 1) * 16);
    const unsigned bRow     = (unsigned)(warpN * 64 + (tile >> 1) * 8 + lt);
    const unsigned bColHalf = (unsigned)((tile & 1) * 16);

    // double-buffered fragments
    uint32_t af[2][4][4];
    uint32_t bf[2][8][2];

    auto load_frags = [&](uint32_t sa, uint32_t sb, int ks, int buf) {
        const unsigned cb = (unsigned)ks * 32u;
        #pragma unroll
        for (int mi = 0; mi < 4; mi++)
            ldsm_x4(sa + swz(aRow + mi * 16u, cb + aColHalf),
                    af[buf][mi][0], af[buf][mi][1], af[buf][mi][2], af[buf][mi][3]);
        #pragma unroll
        for (int p = 0; p < 4; p++)
            ldsm_x4(sb + swz(bRow + p * 16u, cb + bColHalf),
                    bf[buf][2*p][0], bf[buf][2*p][1],
                    bf[buf][2*p+1][0], bf[buf][2*p+1][1]);
    };

    load_stage(0, 0); cp_commit();
    load_stage(1, 1); cp_commit();

    for (int kc = 0; kc < NK_ITERS; kc++) {
        cp_wait<STAGES - 2>();
        __syncthreads();

        const int st = kc % STAGES;
        const uint32_t sa = smem_u32 + st * 2 * STAGE_BYTES;
        const uint32_t sb = sa + STAGE_BYTES;

        // critical path first: ks=0 fragments into buf 0
        load_frags(sa, sb, 0, 0);

        // next stage's global loads (2-iter slack)
        if (kc + STAGES - 1 < NK_ITERS) {
            load_stage((kc + STAGES - 1) % STAGES, kc + STAGES - 1);
            cp_commit();
        }

        // pipelined ks steps: prefetch ks+1 before consuming ks
        #pragma unroll
        for (int ks = 0; ks < 4; ks++) {
            const int cur = ks & 1;
            if (ks < 3) load_frags(sa, sb, ks + 1, cur ^ 1);
            #pragma unroll
            for (int mi = 0; mi < 4; mi++)
                #pragma unroll
                for (int ni = 0; ni < 8; ni++)
                    mma_f16(acc[mi][ni], af[cur][mi], bf[cur][ni]);
        }
    }

    const float sx = 448.f / (g_scales[0] + 1e-6f);
    const float sw = 448.f / (g_scales[1] + 1e-6f);
    const float inv = 1.0f / (sx * sw);

    #pragma unroll
    for (int mi = 0; mi < 4; mi++) {
        const unsigned r0 = mBase + warpM * 64 + mi * 16 + lr;
        #pragma unroll
        for (int ni = 0; ni < 8; ni++) {
            const unsigned c = nBase + warpN * 64 + ni * 8 + lc * 2;
            const float2 bv = *(const float2*)(bias + c);
            const float* a = acc[mi][ni];
            uint16_t p0 = cvt2_e4m3(fmaf(a[0], inv, bv.x), fmaf(a[1], inv, bv.y));
            uint16_t p1 = cvt2_e4m3(fmaf(a[2], inv, bv.x), fmaf(a[3], inv, bv.y));
            float2 f0 = dec2_e4m3(p0);
            float2 f1 = dec2_e4m3(p1);
            *(float2*)(out + (size_t)r0       * NOUT + c) = f0;
            *(float2*)(out + (size_t)(r0 + 8) * NOUT + c) = f1;
        }
    }

    // Re-zero absmax accumulators for next replay (no reader in this kernel).
    if (tid < 2) g_absmax_bits[tid] = 0u;
}

// ---------------------------------------------------------------------------
extern "C" void kernel_launch(void* const* d_in, const int* in_sizes, int n_in,
                              void* d_out, int out_size)
{
    const float* x = (const float*)d_in[0];
    const float* w = (const float*)d_in[1];
    const float* b = (const float*)d_in[2];
    float* out = (float*)d_out;

    absmax_fused_kernel<<<AX_XBLK + AX_WBLK, 256>>>((const float4*)x,
                                                    (const float4*)w);   // #1
    quant_fused_kernel<<<QT_XBLK + QT_WBLK, 256>>>((const float4*)x,
                                                   (const float4*)w);    // #2

    cudaFuncSetAttribute(gemm_kernel, cudaFuncAttributeMaxDynamicSharedMemorySize, SMEM_TOTAL);
    dim3 grid(TOKENS / TM, NOUT / TN);   // (32, 128)
    gemm_kernel<<<grid, NTHREADS, SMEM_TOTAL>>>(b, out);                 // #3

    (void)in_sizes; (void)n_in; (void)out_size;
}